// round 1
// baseline (speedup 1.0000x reference)
#include <cuda_runtime.h>
#include <cstdint>
#include <cstddef>

#define NTOK 8192
#define HDIM 2048
#define NEXP 8
#define KCAP 1024
#define DFF  5461
#define NPAD 5504
#define NSLOT 8192   // NEXP * KCAP

// ---------------- device scratch (static, no allocations) ----------------
__device__ float d_gum[NTOK * NEXP];
__device__ float d_Sm [NTOK * NEXP];
__device__ int   d_idx[NSLOT];
__device__ float d_G  [NSLOT];
__device__ float d_Xg [(size_t)NSLOT * HDIM];
__device__ float d_Wg [(size_t)HDIM * NPAD];
__device__ float d_Wu [(size_t)HDIM * NPAD];
__device__ float d_Wd [(size_t)NPAD * HDIM];
__device__ float d_G1 [(size_t)NSLOT * NPAD];
__device__ float d_U  [(size_t)NSLOT * NPAD];
__device__ float d_O  [(size_t)NSLOT * HDIM];

// ---------------- zero output ----------------
__global__ void zero_kernel(float* p, size_t n) {
    size_t i = (size_t)blockIdx.x * blockDim.x + threadIdx.x;
    if (i < n) p[i] = 0.0f;
}

// ---------------- weight pad-copy ----------------
// SEL: 0 -> d_Wg, 1 -> d_Wu, 2 -> d_Wd
template <int SEL>
__global__ void padcopy_kernel(const float* __restrict__ src,
                               int srows, int scols, int dcols, int total) {
    int i = blockIdx.x * blockDim.x + threadIdx.x;
    if (i >= total) return;
    int r = i / dcols, c = i - r * dcols;
    float v = 0.0f;
    if (r < srows && c < scols) v = src[(size_t)r * scols + c];
    float* dst = (SEL == 0) ? d_Wg : (SEL == 1) ? d_Wu : d_Wd;
    dst[i] = v;
}

// ---------------- Gumbel noise: JAX threefry2x32, partitionable path ----------------
// key = (0, 42). counter per element i: (hi=0, lo=i). bits = x0_out ^ x1_out.
__global__ void gumbel_kernel() {
    unsigned i = blockIdx.x * blockDim.x + threadIdx.x;
    if (i >= NTOK * NEXP) return;
    const uint32_t ks0 = 0u, ks1 = 42u, ks2 = 0u ^ 42u ^ 0x1BD11BDAu;
    uint32_t x0 = 0u + ks0;
    uint32_t x1 = i  + ks1;
#define TF_RND(r) { x0 += x1; x1 = (x1 << (r)) | (x1 >> (32 - (r))); x1 ^= x0; }
    TF_RND(13) TF_RND(15) TF_RND(26) TF_RND(6)   x0 += ks1; x1 += ks2 + 1u;
    TF_RND(17) TF_RND(29) TF_RND(16) TF_RND(24)  x0 += ks2; x1 += ks0 + 2u;
    TF_RND(13) TF_RND(15) TF_RND(26) TF_RND(6)   x0 += ks0; x1 += ks1 + 3u;
    TF_RND(17) TF_RND(29) TF_RND(16) TF_RND(24)  x0 += ks1; x1 += ks2 + 4u;
    TF_RND(13) TF_RND(15) TF_RND(26) TF_RND(6)   x0 += ks2; x1 += ks0 + 5u;
#undef TF_RND
    uint32_t bits = x0 ^ x1;
    float u = __uint_as_float((bits >> 9) | 0x3F800000u) - 1.0f;
    d_gum[i] = -logf(-logf(u + 1e-10f) + 1e-10f);
}

// ---------------- router: logits + gumbel + softmax ----------------
// one warp per token, double accumulators
__global__ void router_kernel(const float* __restrict__ x,
                              const float* __restrict__ rw,
                              const float* __restrict__ rb) {
    int gw = (blockIdx.x * blockDim.x + threadIdx.x) >> 5;
    int lane = threadIdx.x & 31;
    if (gw >= NTOK) return;
    const float* xr = x + (size_t)gw * HDIM;
    double acc[NEXP];
#pragma unroll
    for (int e = 0; e < NEXP; e++) acc[e] = 0.0;
    for (int h = lane; h < HDIM; h += 32) {
        float xv = xr[h];
        const float4* w4 = (const float4*)(rw + (size_t)h * NEXP);
        float4 w0 = w4[0], w1 = w4[1];
        acc[0] += (double)xv * w0.x; acc[1] += (double)xv * w0.y;
        acc[2] += (double)xv * w0.z; acc[3] += (double)xv * w0.w;
        acc[4] += (double)xv * w1.x; acc[5] += (double)xv * w1.y;
        acc[6] += (double)xv * w1.z; acc[7] += (double)xv * w1.w;
    }
#pragma unroll
    for (int off = 16; off; off >>= 1)
#pragma unroll
        for (int e = 0; e < NEXP; e++)
            acc[e] += __shfl_xor_sync(0xffffffffu, acc[e], off);
    if (lane == 0) {
        float hh[NEXP]; float mx = -1e30f;
#pragma unroll
        for (int e = 0; e < NEXP; e++) {
            hh[e] = (float)acc[e] + rb[e] + d_gum[gw * NEXP + e];
            mx = fmaxf(mx, hh[e]);
        }
        float s = 0.0f;
#pragma unroll
        for (int e = 0; e < NEXP; e++) { hh[e] = expf(hh[e] - mx); s += hh[e]; }
        float inv = 1.0f / s;
#pragma unroll
        for (int e = 0; e < NEXP; e++) d_Sm[gw * NEXP + e] = hh[e] * inv;
    }
}

// ---------------- per-expert top-k (bitonic sort, descending, JAX tie-break) ----------------
__global__ void __launch_bounds__(1024) topk_kernel() {
    __shared__ uint32_t        sv[NTOK];   // 32 KB
    __shared__ unsigned short  sid[NTOK];  // 16 KB
    int e = blockIdx.x;
    int tid = threadIdx.x;
    for (int i = tid; i < NTOK; i += 1024) {
        sv[i]  = __float_as_uint(d_Sm[(size_t)i * NEXP + e]);  // softmax >= 0: bits monotone
        sid[i] = (unsigned short)i;
    }
    __syncthreads();
    for (int k = 2; k <= NTOK; k <<= 1) {
        for (int j = k >> 1; j > 0; j >>= 1) {
            for (int i = tid; i < NTOK; i += 1024) {
                int ixj = i ^ j;
                if (ixj > i) {
                    uint32_t av = sv[i], bv = sv[ixj];
                    unsigned short ai = sid[i], bi = sid[ixj];
                    // strict less (descending key): value, ties -> lower index ranks higher
                    bool aLess = (av < bv) || (av == bv && ai > bi);
                    bool up = ((i & k) == 0);   // descending segments
                    if (up ? aLess : !aLess) {
                        sv[i] = bv; sv[ixj] = av;
                        sid[i] = bi; sid[ixj] = ai;
                    }
                }
            }
            __syncthreads();
        }
    }
    if (tid < KCAP) {
        d_idx[e * KCAP + tid] = (int)sid[tid];
        d_G[e * KCAP + tid]   = __uint_as_float(sv[tid]);
    }
}

// ---------------- gather routed tokens ----------------
__global__ void gather_kernel(const float* __restrict__ x) {
    int r = blockIdx.x;
    int tok = d_idx[r];
    const float4* src = (const float4*)(x + (size_t)tok * HDIM);
    float4* dst = (float4*)(d_Xg + (size_t)r * HDIM);
    for (int i = threadIdx.x; i < HDIM / 4; i += blockDim.x) dst[i] = src[i];
}

// ---------------- tf32 tensor-core GEMM: C[M,N] = A[M,K] * B[K,N] ----------------
// 128x128x16 block tile, 256 threads = 8 warps (4M x 2N), warp tile 32x64,
// mma.sync.m16n8k8 tf32. All dims padded -> no bounds checks.
__device__ __forceinline__ uint32_t f2tf(float x) {
    uint32_t r; asm("cvt.rna.tf32.f32 %0, %1;" : "=r"(r) : "f"(x)); return r;
}

// SEL: 0: Xg*Wg->G1   1: Xg*Wu->U   2: G1*Wd->O
template <int SEL>
__global__ void __launch_bounds__(256) gemm_tf32(int K, int lda, int ldb, int ldc) {
    const float* __restrict__ A = (SEL == 2) ? d_G1 : d_Xg;
    const float* __restrict__ B = (SEL == 0) ? d_Wg : (SEL == 1) ? d_Wu : d_Wd;
    float* __restrict__ C       = (SEL == 0) ? d_G1 : (SEL == 1) ? d_U  : d_O;

    __shared__ __align__(16) float As[16][132];
    __shared__ __align__(16) float Bs[16][132];

    int tid = threadIdx.x;
    int wid = tid >> 5, lane = tid & 31;
    int wm = (wid >> 1) * 32;
    int wn = (wid & 1) * 64;
    int gp = lane >> 2, tg = lane & 3;
    int bm = blockIdx.y * 128;
    int bn = blockIdx.x * 128;

    float c[2][8][4];
#pragma unroll
    for (int mi = 0; mi < 2; mi++)
#pragma unroll
        for (int ni = 0; ni < 8; ni++)
#pragma unroll
            for (int q = 0; q < 4; q++) c[mi][ni][q] = 0.0f;

    const float* Ab = A + (size_t)bm * lda;
    const float* Bb = B + bn;

    for (int k0 = 0; k0 < K; k0 += 16) {
#pragma unroll
        for (int i = 0; i < 2; i++) {     // A tile: 128 x 16, store transposed
            int id = tid + i * 256;
            int r  = id >> 2;
            int c4 = (id & 3) << 2;
            float4 v = *(const float4*)(Ab + (size_t)r * lda + k0 + c4);
            As[c4 + 0][r] = v.x; As[c4 + 1][r] = v.y;
            As[c4 + 2][r] = v.z; As[c4 + 3][r] = v.w;
        }
#pragma unroll
        for (int i = 0; i < 2; i++) {     // B tile: 16 x 128
            int id = tid + i * 256;
            int r  = id >> 5;
            int c4 = (id & 31) << 2;
            *(float4*)&Bs[r][c4] = *(const float4*)(Bb + (size_t)(k0 + r) * ldb + c4);
        }
        __syncthreads();

#pragma unroll
        for (int kk = 0; kk < 16; kk += 8) {
            uint32_t a[2][4], b[8][2];
#pragma unroll
            for (int mi = 0; mi < 2; mi++) {
                int m0 = wm + mi * 16 + gp;
                a[mi][0] = f2tf(As[kk + tg    ][m0    ]);
                a[mi][1] = f2tf(As[kk + tg    ][m0 + 8]);
                a[mi][2] = f2tf(As[kk + tg + 4][m0    ]);
                a[mi][3] = f2tf(As[kk + tg + 4][m0 + 8]);
            }
#pragma unroll
            for (int ni = 0; ni < 8; ni++) {
                int n0 = wn + ni * 8 + gp;
                b[ni][0] = f2tf(Bs[kk + tg    ][n0]);
                b[ni][1] = f2tf(Bs[kk + tg + 4][n0]);
            }
#pragma unroll
            for (int mi = 0; mi < 2; mi++)
#pragma unroll
                for (int ni = 0; ni < 8; ni++)
                    asm volatile(
                        "mma.sync.aligned.m16n8k8.row.col.f32.tf32.tf32.f32 "
                        "{%0,%1,%2,%3}, {%4,%5,%6,%7}, {%8,%9}, {%0,%1,%2,%3};"
                        : "+f"(c[mi][ni][0]), "+f"(c[mi][ni][1]),
                          "+f"(c[mi][ni][2]), "+f"(c[mi][ni][3])
                        : "r"(a[mi][0]), "r"(a[mi][1]), "r"(a[mi][2]), "r"(a[mi][3]),
                          "r"(b[ni][0]), "r"(b[ni][1]));
        }
        __syncthreads();
    }

#pragma unroll
    for (int mi = 0; mi < 2; mi++) {
        int row = bm + wm + mi * 16 + gp;
#pragma unroll
        for (int ni = 0; ni < 8; ni++) {
            int col = bn + wn + ni * 8 + 2 * tg;
            *(float2*)(C + (size_t)row * ldc + col)       = make_float2(c[mi][ni][0], c[mi][ni][1]);
            *(float2*)(C + (size_t)(row + 8) * ldc + col) = make_float2(c[mi][ni][2], c[mi][ni][3]);
        }
    }
}

// ---------------- silu(gate+bg) * (up+bu) -> d_G1 (pad cols zeroed) ----------------
__global__ void silu_kernel(const float* __restrict__ bg, const float* __restrict__ bu) {
    int n = blockIdx.x * blockDim.x + threadIdx.x;
    int r = blockIdx.y;
    if (n >= NPAD) return;
    size_t off = (size_t)r * NPAD + n;
    float outv = 0.0f;
    if (n < DFF) {
        float g = d_G1[off] + bg[n];
        float u = d_U[off]  + bu[n];
        outv = g * (1.0f / (1.0f + expf(-g))) * u;
    }
    d_G1[off] = outv;
}

// ---------------- weighted scatter-add ----------------
__global__ void scatter_kernel(const float* __restrict__ bd, float* __restrict__ out) {
    int r = blockIdx.x;
    int tok = d_idx[r];
    float g = d_G[r];
    const float* o = d_O + (size_t)r * HDIM;
    float* dst = out + (size_t)tok * HDIM;
    for (int h = threadIdx.x; h < HDIM; h += blockDim.x)
        atomicAdd(dst + h, g * (o[h] + bd[h]));
}

// ---------------- launch ----------------
extern "C" void kernel_launch(void* const* d_in, const int* in_sizes, int n_in,
                              void* d_out, int out_size) {
    const float* x  = (const float*)d_in[0];
    const float* rw = (const float*)d_in[1];
    const float* rb = (const float*)d_in[2];
    const float* wg = (const float*)d_in[3];
    const float* bg = (const float*)d_in[4];
    const float* wu = (const float*)d_in[5];
    const float* bu = (const float*)d_in[6];
    const float* wd = (const float*)d_in[7];
    const float* bd = (const float*)d_in[8];
    float* out = (float*)d_out;

    zero_kernel<<<(out_size + 255) / 256, 256>>>(out, (size_t)out_size);

    int totGU = HDIM * NPAD;       // 2048*5504
    int totD  = NPAD * HDIM;       // 5504*2048
    padcopy_kernel<0><<<(totGU + 255) / 256, 256>>>(wg, HDIM, DFF, NPAD, totGU);
    padcopy_kernel<1><<<(totGU + 255) / 256, 256>>>(wu, HDIM, DFF, NPAD, totGU);
    padcopy_kernel<2><<<(totD  + 255) / 256, 256>>>(wd, DFF, HDIM, HDIM, totD);

    gumbel_kernel<<<(NTOK * NEXP + 255) / 256, 256>>>();
    router_kernel<<<NTOK / 8, 256>>>(x, rw, rb);
    topk_kernel<<<NEXP, 1024>>>();
    gather_kernel<<<NSLOT, 256>>>(x);

    dim3 g12(NPAD / 128, NSLOT / 128);   // (43, 64)
    gemm_tf32<0><<<g12, 256>>>(HDIM, HDIM, NPAD, NPAD);
    gemm_tf32<1><<<g12, 256>>>(HDIM, HDIM, NPAD, NPAD);

    silu_kernel<<<dim3((NPAD + 255) / 256, NSLOT), 256>>>(bg, bu);

    dim3 g3(HDIM / 128, NSLOT / 128);    // (16, 64)
    gemm_tf32<2><<<g3, 256>>>(NPAD, NPAD, HDIM, HDIM);

    scatter_kernel<<<NSLOT, 256>>>(bd, out);
}

// round 3
// speedup vs baseline: 1.6331x; 1.6331x over previous
#include <cuda_runtime.h>
#include <cstdint>
#include <cstddef>

#define NTOK 8192
#define HDIM 2048
#define NEXP 8
#define KCAP 1024
#define DFF  5461
#define NPAD 5504
#define NSLOT 8192   // NEXP * KCAP

// ---------------- device scratch (static, no allocations) ----------------
__device__ float d_gum[NTOK * NEXP];
__device__ float d_Sm [NTOK * NEXP];
__device__ int   d_idx[NSLOT];
__device__ float d_G  [NSLOT];
__device__ float d_Xg [(size_t)NSLOT * HDIM];   // gathered tokens, tf32-rounded
__device__ float d_Wg [(size_t)HDIM * NPAD];    // w_gate  [K=2048][N=5504] tf32, col-pad
__device__ float d_Wu [(size_t)HDIM * NPAD];    // w_up    same
__device__ float d_Wd [(size_t)NPAD * HDIM];    // w_down  [K=5504][N=2048] tf32, row-pad
__device__ float d_G1 [(size_t)NSLOT * NPAD];   // gate raw, then silu(g)*up (tf32-rounded)

// ---------------- helpers ----------------
__device__ __forceinline__ uint32_t smem_u32(const void* p) {
    uint32_t a;
    asm("{ .reg .u64 t; cvta.to.shared.u64 t, %1; cvt.u32.u64 %0, t; }" : "=r"(a) : "l"(p));
    return a;
}
__device__ __forceinline__ uint32_t f2tf(float x) {
    uint32_t r; asm("cvt.rna.tf32.f32 %0, %1;" : "=r"(r) : "f"(x)); return r;
}
__device__ __forceinline__ float tf32r(float x) { return __uint_as_float(f2tf(x)); }
__device__ __forceinline__ uint32_t lds32(uint32_t a) {
    uint32_t v; asm("ld.shared.b32 %0, [%1];" : "=r"(v) : "r"(a)); return v;
}
__device__ __forceinline__ void cpasync16(uint32_t dst, const void* src) {
    asm volatile("cp.async.cg.shared.global [%0], [%1], 16;" :: "r"(dst), "l"(src) : "memory");
}
#define CP_COMMIT()  asm volatile("cp.async.commit_group;" ::: "memory")
#define CP_WAIT1()   asm volatile("cp.async.wait_group 1;" ::: "memory")

// ---------------- zero output ----------------
__global__ void zero_kernel(float* p, size_t n) {
    size_t i = (size_t)blockIdx.x * blockDim.x + threadIdx.x;
    if (i < n) p[i] = 0.0f;
}

// ---------------- pad + tf32-convert weights (no transpose) ----------------
// SEL 0: wg [2048][5461] -> d_Wg [2048][5504]  (pad cols)
// SEL 1: wu -> d_Wu same
// SEL 2: wd [5461][2048] -> d_Wd [5504][2048]  (pad rows)
template <int SEL>
__global__ void padconv_kernel(const float* __restrict__ src, int total) {
    int i = blockIdx.x * blockDim.x + threadIdx.x;
    if (i >= total) return;
    float v = 0.0f;
    if (SEL < 2) {
        int r = i / NPAD, c = i - r * NPAD;
        if (c < DFF) v = src[(size_t)r * DFF + c];
    } else {
        int r = i / HDIM;
        if (r < DFF) v = src[i - (size_t)0];  // same linear index while r<DFF
    }
    float* dst = (SEL == 0) ? d_Wg : (SEL == 1) ? d_Wu : d_Wd;
    dst[i] = tf32r(v);
}

// ---------------- Gumbel noise: JAX threefry2x32 ----------------
__global__ void gumbel_kernel() {
    unsigned i = blockIdx.x * blockDim.x + threadIdx.x;
    if (i >= NTOK * NEXP) return;
    const uint32_t ks0 = 0u, ks1 = 42u, ks2 = 0u ^ 42u ^ 0x1BD11BDAu;
    uint32_t x0 = 0u + ks0;
    uint32_t x1 = i  + ks1;
#define TF_RND(r) { x0 += x1; x1 = (x1 << (r)) | (x1 >> (32 - (r))); x1 ^= x0; }
    TF_RND(13) TF_RND(15) TF_RND(26) TF_RND(6)   x0 += ks1; x1 += ks2 + 1u;
    TF_RND(17) TF_RND(29) TF_RND(16) TF_RND(24)  x0 += ks2; x1 += ks0 + 2u;
    TF_RND(13) TF_RND(15) TF_RND(26) TF_RND(6)   x0 += ks0; x1 += ks1 + 3u;
    TF_RND(17) TF_RND(29) TF_RND(16) TF_RND(24)  x0 += ks1; x1 += ks2 + 4u;
    TF_RND(13) TF_RND(15) TF_RND(26) TF_RND(6)   x0 += ks2; x1 += ks0 + 5u;
#undef TF_RND
    uint32_t bits = x0 ^ x1;
    float u = __uint_as_float((bits >> 9) | 0x3F800000u) - 1.0f;
    d_gum[i] = -logf(-logf(u + 1e-10f) + 1e-10f);
}

// ---------------- router ----------------
__global__ void router_kernel(const float* __restrict__ x,
                              const float* __restrict__ rw,
                              const float* __restrict__ rb) {
    int gw = (blockIdx.x * blockDim.x + threadIdx.x) >> 5;
    int lane = threadIdx.x & 31;
    if (gw >= NTOK) return;
    const float* xr = x + (size_t)gw * HDIM;
    double acc[NEXP];
#pragma unroll
    for (int e = 0; e < NEXP; e++) acc[e] = 0.0;
    for (int h = lane; h < HDIM; h += 32) {
        float xv = xr[h];
        const float4* w4 = (const float4*)(rw + (size_t)h * NEXP);
        float4 w0 = w4[0], w1 = w4[1];
        acc[0] += (double)xv * w0.x; acc[1] += (double)xv * w0.y;
        acc[2] += (double)xv * w0.z; acc[3] += (double)xv * w0.w;
        acc[4] += (double)xv * w1.x; acc[5] += (double)xv * w1.y;
        acc[6] += (double)xv * w1.z; acc[7] += (double)xv * w1.w;
    }
#pragma unroll
    for (int off = 16; off; off >>= 1)
#pragma unroll
        for (int e = 0; e < NEXP; e++)
            acc[e] += __shfl_xor_sync(0xffffffffu, acc[e], off);
    if (lane == 0) {
        float hh[NEXP]; float mx = -1e30f;
#pragma unroll
        for (int e = 0; e < NEXP; e++) {
            hh[e] = (float)acc[e] + rb[e] + d_gum[gw * NEXP + e];
            mx = fmaxf(mx, hh[e]);
        }
        float s = 0.0f;
#pragma unroll
        for (int e = 0; e < NEXP; e++) { hh[e] = expf(hh[e] - mx); s += hh[e]; }
        float inv = 1.0f / s;
#pragma unroll
        for (int e = 0; e < NEXP; e++) d_Sm[gw * NEXP + e] = hh[e] * inv;
    }
}

// ---------------- per-expert top-k (bitonic) ----------------
__global__ void __launch_bounds__(1024) topk_kernel() {
    __shared__ uint32_t       sv[NTOK];
    __shared__ unsigned short sid[NTOK];
    int e = blockIdx.x;
    int tid = threadIdx.x;
    for (int i = tid; i < NTOK; i += 1024) {
        sv[i]  = __float_as_uint(d_Sm[(size_t)i * NEXP + e]);
        sid[i] = (unsigned short)i;
    }
    __syncthreads();
    for (int k = 2; k <= NTOK; k <<= 1) {
        for (int j = k >> 1; j > 0; j >>= 1) {
            for (int i = tid; i < NTOK; i += 1024) {
                int ixj = i ^ j;
                if (ixj > i) {
                    uint32_t av = sv[i], bv = sv[ixj];
                    unsigned short ai = sid[i], bi = sid[ixj];
                    bool aLess = (av < bv) || (av == bv && ai > bi);
                    bool up = ((i & k) == 0);
                    if (up ? aLess : !aLess) {
                        sv[i] = bv; sv[ixj] = av;
                        sid[i] = bi; sid[ixj] = ai;
                    }
                }
            }
            __syncthreads();
        }
    }
    if (tid < KCAP) {
        d_idx[e * KCAP + tid] = (int)sid[tid];
        d_G[e * KCAP + tid]   = __uint_as_float(sv[tid]);
    }
}

// ---------------- gather routed tokens (tf32-rounded) ----------------
__global__ void gather_kernel(const float* __restrict__ x) {
    int r = blockIdx.x;
    int tok = d_idx[r];
    const float4* src = (const float4*)(x + (size_t)tok * HDIM);
    float4* dst = (float4*)(d_Xg + (size_t)r * HDIM);
    for (int i = threadIdx.x; i < HDIM / 4; i += blockDim.x) {
        float4 v = src[i];
        dst[i] = make_float4(tf32r(v.x), tf32r(v.y), tf32r(v.z), tf32r(v.w));
    }
}

// ---------------- pipelined tf32 mma.sync GEMM ----------------
// C[M,N] = A[M,K] * B[K,N]. CTA tile 128x128, BK=32, 3-stage cp.async.
// 128 threads = 4 warps, each 64x64 (mi 0..3 of m16, ni 0..7 of n8).
// SEL 0: Xg*Wg -> d_G1 raw
// SEL 1: Xg*Wu -> d_G1 = tf32(silu(d_G1+bg)*(acc+bu)), pad cols zeroed
// SEL 2: G1*Wd -> atomicAdd(out[tok], g*(acc+bd))
#define ABYTES 16384
#define BROW   528
#define BBYTES (32 * BROW)          // 16896
#define STG    (ABYTES + BBYTES)    // 33280
#define NS     3
#define DYN    (NS * STG)           // 99840

__device__ __forceinline__ void load_stage(uint32_t sbase, int s,
                                           const float* Ag, int lda,
                                           const float* Bg, int ldb,
                                           int i, int tid) {
    uint32_t st = sbase + s * STG;
    const float* Asrc = Ag + i * 32;
    const float* Bsrc = Bg + (size_t)(i * 32) * ldb;
#pragma unroll
    for (int t = 0; t < 8; t++) {            // A: 128 rows x 32 floats, swizzled
        int idx = tid + t * 128;
        int m = idx >> 3, k4 = idx & 7;
        uint32_t dst = st + (((uint32_t)(m * 128 + k4 * 16)) ^ ((uint32_t)(m & 7) << 4));
        cpasync16(dst, Asrc + (size_t)m * lda + k4 * 4);
    }
#pragma unroll
    for (int t = 0; t < 8; t++) {            // B: 32 rows x 128 floats, padded rows
        int idx = tid + t * 128;
        int k = idx >> 5, n16 = idx & 31;
        uint32_t dst = st + ABYTES + k * BROW + n16 * 16;
        cpasync16(dst, Bsrc + (size_t)k * ldb + n16 * 4);
    }
}

template <int SEL>
__global__ void __launch_bounds__(128) gemm_mma(
    int K, int lda, int ldb,
    const float* __restrict__ bg, const float* __restrict__ bu,
    const float* __restrict__ bdn, float* __restrict__ out)
{
    extern __shared__ __align__(1024) char dsm[];
    const float* A = (SEL == 2) ? d_G1 : d_Xg;
    const float* B = (SEL == 0) ? d_Wg : (SEL == 1) ? d_Wu : d_Wd;

    uint32_t sbase = smem_u32(dsm);
    int tid = threadIdx.x, wid = tid >> 5, lane = tid & 31;
    int gp = lane >> 2, tg = lane & 3;
    int wm = (wid >> 1) * 64, wn = (wid & 1) * 64;
    int bm = blockIdx.y * 128, bn = blockIdx.x * 128;

    const float* Ag = A + (size_t)bm * lda;
    const float* Bg = B + bn;
    const int NC = K >> 5;

    float c[4][8][4];
#pragma unroll
    for (int mi = 0; mi < 4; mi++)
#pragma unroll
        for (int ni = 0; ni < 8; ni++)
#pragma unroll
            for (int q = 0; q < 4; q++) c[mi][ni][q] = 0.0f;

    load_stage(sbase, 0, Ag, lda, Bg, ldb, 0, tid); CP_COMMIT();
    load_stage(sbase, 1, Ag, lda, Bg, ldb, 1, tid); CP_COMMIT();

    for (int i = 0; i < NC; i++) {
        CP_WAIT1();
        __syncthreads();
        if (i + 2 < NC) load_stage(sbase, (i + 2) % NS, Ag, lda, Bg, ldb, i + 2, tid);
        CP_COMMIT();

        uint32_t abase = sbase + (i % NS) * STG;
        uint32_t bbase = abase + ABYTES;
        uint32_t axor = (uint32_t)gp << 4;

#pragma unroll
        for (int kk = 0; kk < 32; kk += 8) {
            int k0 = kk + tg;
            uint32_t kof0 = ((uint32_t)(k0 * 4)) ^ axor;
            uint32_t kof1 = ((uint32_t)((k0 + 4) * 4)) ^ axor;
            uint32_t a[4][4];
#pragma unroll
            for (int mi = 0; mi < 4; mi++) {
                uint32_t r0 = abase + (uint32_t)((wm + mi * 16 + gp) * 128);
                a[mi][0] = lds32(r0 + kof0);
                a[mi][1] = lds32(r0 + 8 * 128 + kof0);
                a[mi][2] = lds32(r0 + kof1);
                a[mi][3] = lds32(r0 + 8 * 128 + kof1);
            }
            uint32_t b[8][2];
#pragma unroll
            for (int ni = 0; ni < 8; ni++) {
                uint32_t nof = bbase + (uint32_t)((wn + ni * 8 + gp) * 4);
                b[ni][0] = lds32(nof + (uint32_t)(k0 * BROW));
                b[ni][1] = lds32(nof + (uint32_t)((k0 + 4) * BROW));
            }
#pragma unroll
            for (int mi = 0; mi < 4; mi++)
#pragma unroll
                for (int ni = 0; ni < 8; ni++)
                    asm volatile(
                        "mma.sync.aligned.m16n8k8.row.col.f32.tf32.tf32.f32 "
                        "{%0,%1,%2,%3}, {%4,%5,%6,%7}, {%8,%9}, {%0,%1,%2,%3};"
                        : "+f"(c[mi][ni][0]), "+f"(c[mi][ni][1]),
                          "+f"(c[mi][ni][2]), "+f"(c[mi][ni][3])
                        : "r"(a[mi][0]), "r"(a[mi][1]), "r"(a[mi][2]), "r"(a[mi][3]),
                          "r"(b[ni][0]), "r"(b[ni][1]));
        }
    }

    // ---------------- epilogue ----------------
#pragma unroll
    for (int mi = 0; mi < 4; mi++) {
        int row = bm + wm + mi * 16 + gp;
        int tok0 = 0, tok1 = 0; float g0 = 0.f, g1 = 0.f;
        if (SEL == 2) {
            tok0 = d_idx[row];     g0 = d_G[row];
            tok1 = d_idx[row + 8]; g1 = d_G[row + 8];
        }
#pragma unroll
        for (int ni = 0; ni < 8; ni++) {
            int col = bn + wn + ni * 8 + 2 * tg;
            if (SEL == 0) {
                *(float2*)(d_G1 + (size_t)row * NPAD + col)       = make_float2(c[mi][ni][0], c[mi][ni][1]);
                *(float2*)(d_G1 + (size_t)(row + 8) * NPAD + col) = make_float2(c[mi][ni][2], c[mi][ni][3]);
            } else if (SEL == 1) {
#pragma unroll
                for (int h = 0; h < 2; h++) {
                    int r2 = row + h * 8;
                    float* crow = d_G1 + (size_t)r2 * NPAD + col;
                    float2 gv = *(const float2*)crow;
                    float o0 = 0.f, o1 = 0.f;
                    if (col < DFF) {
                        float gate = gv.x + bg[col];
                        float up   = c[mi][ni][h * 2 + 0] + bu[col];
                        o0 = tf32r(gate * (1.0f / (1.0f + expf(-gate))) * up);
                    }
                    if (col + 1 < DFF) {
                        float gate = gv.y + bg[col + 1];
                        float up   = c[mi][ni][h * 2 + 1] + bu[col + 1];
                        o1 = tf32r(gate * (1.0f / (1.0f + expf(-gate))) * up);
                    }
                    *(float2*)crow = make_float2(o0, o1);
                }
            } else {
                float b0 = bdn[col], b1 = bdn[col + 1];
                float* o0 = out + (size_t)tok0 * HDIM + col;
                atomicAdd(o0,     g0 * (c[mi][ni][0] + b0));
                atomicAdd(o0 + 1, g0 * (c[mi][ni][1] + b1));
                float* o1 = out + (size_t)tok1 * HDIM + col;
                atomicAdd(o1,     g1 * (c[mi][ni][2] + b0));
                atomicAdd(o1 + 1, g1 * (c[mi][ni][3] + b1));
            }
        }
    }
}

// ---------------- launch ----------------
extern "C" void kernel_launch(void* const* d_in, const int* in_sizes, int n_in,
                              void* d_out, int out_size) {
    const float* x  = (const float*)d_in[0];
    const float* rw = (const float*)d_in[1];
    const float* rb = (const float*)d_in[2];
    const float* wg = (const float*)d_in[3];
    const float* bg = (const float*)d_in[4];
    const float* wu = (const float*)d_in[5];
    const float* bu = (const float*)d_in[6];
    const float* wd = (const float*)d_in[7];
    const float* bd = (const float*)d_in[8];
    float* out = (float*)d_out;

    cudaFuncSetAttribute(gemm_mma<0>, cudaFuncAttributeMaxDynamicSharedMemorySize, DYN);
    cudaFuncSetAttribute(gemm_mma<1>, cudaFuncAttributeMaxDynamicSharedMemorySize, DYN);
    cudaFuncSetAttribute(gemm_mma<2>, cudaFuncAttributeMaxDynamicSharedMemorySize, DYN);

    zero_kernel<<<((size_t)out_size + 255) / 256, 256>>>(out, (size_t)out_size);

    int totGU = HDIM * NPAD;
    int totD  = NPAD * HDIM;
    padconv_kernel<0><<<(totGU + 255) / 256, 256>>>(wg, totGU);
    padconv_kernel<1><<<(totGU + 255) / 256, 256>>>(wu, totGU);
    padconv_kernel<2><<<(totD  + 255) / 256, 256>>>(wd, totD);

    gumbel_kernel<<<(NTOK * NEXP + 255) / 256, 256>>>();
    router_kernel<<<NTOK / 8, 256>>>(x, rw, rb);
    topk_kernel<<<NEXP, 1024>>>();
    gather_kernel<<<NSLOT, 256>>>(x);

    dim3 g12(NPAD / 128, NSLOT / 128);   // (43, 64)
    gemm_mma<0><<<g12, 128, DYN>>>(HDIM, HDIM, NPAD, nullptr, nullptr, nullptr, nullptr);
    gemm_mma<1><<<g12, 128, DYN>>>(HDIM, HDIM, NPAD, bg, bu, nullptr, nullptr);

    dim3 g3(HDIM / 128, NSLOT / 128);    // (16, 64)
    gemm_mma<2><<<g3, 128, DYN>>>(NPAD, NPAD, HDIM, nullptr, nullptr, bd, out);
}

// round 4
// speedup vs baseline: 2.9579x; 1.8113x over previous
#include <cuda_runtime.h>
#include <cuda_fp16.h>
#include <cstdint>
#include <cstddef>

#define NTOK 8192
#define HDIM 2048
#define NEXP 8
#define KCAP 1024
#define DFF  5461
#define NPAD 5504
#define NSLOT 8192   // NEXP * KCAP

// ---------------- device scratch (static, no allocations) ----------------
__device__ float  d_gum[NTOK * NEXP];
__device__ float  d_Sm [NTOK * NEXP];
__device__ int    d_idx[NSLOT];
__device__ float  d_G  [NSLOT];
__device__ __half d_Xg [(size_t)NSLOT * HDIM];   // gathered tokens fp16
__device__ __half d_Wg [(size_t)HDIM * NPAD];    // w_gate  [K=2048][N=5504] fp16
__device__ __half d_Wu [(size_t)HDIM * NPAD];    // w_up
__device__ __half d_Wd [(size_t)NPAD * HDIM];    // w_down  [K=5504][N=2048] fp16
__device__ float  d_G1f[(size_t)NSLOT * NPAD];   // gate pre-activation fp32
__device__ __half d_Hh [(size_t)NSLOT * NPAD];   // silu(g)*up fp16

// ---------------- helpers ----------------
__device__ __forceinline__ uint32_t smem_u32(const void* p) {
    uint32_t a;
    asm("{ .reg .u64 t; cvta.to.shared.u64 t, %1; cvt.u32.u64 %0, t; }" : "=r"(a) : "l"(p));
    return a;
}
__device__ __forceinline__ void cpasync16(uint32_t dst, const void* src) {
    asm volatile("cp.async.cg.shared.global [%0], [%1], 16;" :: "r"(dst), "l"(src) : "memory");
}
#define CP_COMMIT()  asm volatile("cp.async.commit_group;" ::: "memory")
#define CP_WAIT1()   asm volatile("cp.async.wait_group 1;" ::: "memory")

__device__ __forceinline__ void ldm_x4(uint32_t* r, uint32_t a) {
    asm volatile("ldmatrix.sync.aligned.m8n8.x4.shared.b16 {%0,%1,%2,%3}, [%4];"
                 : "=r"(r[0]), "=r"(r[1]), "=r"(r[2]), "=r"(r[3]) : "r"(a));
}
__device__ __forceinline__ void ldm_x4_t(uint32_t* r, uint32_t a) {
    asm volatile("ldmatrix.sync.aligned.m8n8.x4.trans.shared.b16 {%0,%1,%2,%3}, [%4];"
                 : "=r"(r[0]), "=r"(r[1]), "=r"(r[2]), "=r"(r[3]) : "r"(a));
}
__device__ __forceinline__ void mma16816(float* c, const uint32_t* a, const uint32_t* b) {
    asm volatile(
        "mma.sync.aligned.m16n8k16.row.col.f32.f16.f16.f32 "
        "{%0,%1,%2,%3}, {%4,%5,%6,%7}, {%8,%9}, {%0,%1,%2,%3};"
        : "+f"(c[0]), "+f"(c[1]), "+f"(c[2]), "+f"(c[3])
        : "r"(a[0]), "r"(a[1]), "r"(a[2]), "r"(a[3]), "r"(b[0]), "r"(b[1]));
}

// ---------------- zero output ----------------
__global__ void zero_kernel(float* p, size_t n) {
    size_t i = (size_t)blockIdx.x * blockDim.x + threadIdx.x;
    if (i < n) p[i] = 0.0f;
}

// ---------------- pad + fp16-convert weights ----------------
// SEL 0: wg [2048][5461] -> d_Wg [2048][5504]; SEL 1: wu; SEL 2: wd [5461][2048] -> [5504][2048]
template <int SEL>
__global__ void padconv_kernel(const float* __restrict__ src, int total) {
    int i = blockIdx.x * blockDim.x + threadIdx.x;
    if (i >= total) return;
    float v = 0.0f;
    if (SEL < 2) {
        int r = i / NPAD, c = i - r * NPAD;
        if (c < DFF) v = src[(size_t)r * DFF + c];
    } else {
        int r = i / HDIM;
        if (r < DFF) v = src[i];
    }
    __half* dst = (SEL == 0) ? d_Wg : (SEL == 1) ? d_Wu : d_Wd;
    dst[i] = __float2half_rn(v);
}

// ---------------- Gumbel noise: JAX threefry2x32 ----------------
__global__ void gumbel_kernel() {
    unsigned i = blockIdx.x * blockDim.x + threadIdx.x;
    if (i >= NTOK * NEXP) return;
    const uint32_t ks0 = 0u, ks1 = 42u, ks2 = 0u ^ 42u ^ 0x1BD11BDAu;
    uint32_t x0 = 0u + ks0;
    uint32_t x1 = i  + ks1;
#define TF_RND(r) { x0 += x1; x1 = (x1 << (r)) | (x1 >> (32 - (r))); x1 ^= x0; }
    TF_RND(13) TF_RND(15) TF_RND(26) TF_RND(6)   x0 += ks1; x1 += ks2 + 1u;
    TF_RND(17) TF_RND(29) TF_RND(16) TF_RND(24)  x0 += ks2; x1 += ks0 + 2u;
    TF_RND(13) TF_RND(15) TF_RND(26) TF_RND(6)   x0 += ks0; x1 += ks1 + 3u;
    TF_RND(17) TF_RND(29) TF_RND(16) TF_RND(24)  x0 += ks1; x1 += ks2 + 4u;
    TF_RND(13) TF_RND(15) TF_RND(26) TF_RND(6)   x0 += ks2; x1 += ks0 + 5u;
#undef TF_RND
    uint32_t bits = x0 ^ x1;
    float u = __uint_as_float((bits >> 9) | 0x3F800000u) - 1.0f;
    d_gum[i] = -logf(-logf(u + 1e-10f) + 1e-10f);
}

// ---------------- router ----------------
__global__ void router_kernel(const float* __restrict__ x,
                              const float* __restrict__ rw,
                              const float* __restrict__ rb) {
    int gw = (blockIdx.x * blockDim.x + threadIdx.x) >> 5;
    int lane = threadIdx.x & 31;
    if (gw >= NTOK) return;
    const float* xr = x + (size_t)gw * HDIM;
    double acc[NEXP];
#pragma unroll
    for (int e = 0; e < NEXP; e++) acc[e] = 0.0;
    for (int h = lane; h < HDIM; h += 32) {
        float xv = xr[h];
        const float4* w4 = (const float4*)(rw + (size_t)h * NEXP);
        float4 w0 = w4[0], w1 = w4[1];
        acc[0] += (double)xv * w0.x; acc[1] += (double)xv * w0.y;
        acc[2] += (double)xv * w0.z; acc[3] += (double)xv * w0.w;
        acc[4] += (double)xv * w1.x; acc[5] += (double)xv * w1.y;
        acc[6] += (double)xv * w1.z; acc[7] += (double)xv * w1.w;
    }
#pragma unroll
    for (int off = 16; off; off >>= 1)
#pragma unroll
        for (int e = 0; e < NEXP; e++)
            acc[e] += __shfl_xor_sync(0xffffffffu, acc[e], off);
    if (lane == 0) {
        float hh[NEXP]; float mx = -1e30f;
#pragma unroll
        for (int e = 0; e < NEXP; e++) {
            hh[e] = (float)acc[e] + rb[e] + d_gum[gw * NEXP + e];
            mx = fmaxf(mx, hh[e]);
        }
        float s = 0.0f;
#pragma unroll
        for (int e = 0; e < NEXP; e++) { hh[e] = expf(hh[e] - mx); s += hh[e]; }
        float inv = 1.0f / s;
#pragma unroll
        for (int e = 0; e < NEXP; e++) d_Sm[gw * NEXP + e] = hh[e] * inv;
    }
}

// ---------------- per-expert top-k (bitonic) ----------------
__global__ void __launch_bounds__(1024) topk_kernel() {
    __shared__ uint32_t       sv[NTOK];
    __shared__ unsigned short sid[NTOK];
    int e = blockIdx.x;
    int tid = threadIdx.x;
    for (int i = tid; i < NTOK; i += 1024) {
        sv[i]  = __float_as_uint(d_Sm[(size_t)i * NEXP + e]);
        sid[i] = (unsigned short)i;
    }
    __syncthreads();
    for (int k = 2; k <= NTOK; k <<= 1) {
        for (int j = k >> 1; j > 0; j >>= 1) {
            for (int i = tid; i < NTOK; i += 1024) {
                int ixj = i ^ j;
                if (ixj > i) {
                    uint32_t av = sv[i], bv = sv[ixj];
                    unsigned short ai = sid[i], bi = sid[ixj];
                    bool aLess = (av < bv) || (av == bv && ai > bi);
                    bool up = ((i & k) == 0);
                    if (up ? aLess : !aLess) {
                        sv[i] = bv; sv[ixj] = av;
                        sid[i] = bi; sid[ixj] = ai;
                    }
                }
            }
            __syncthreads();
        }
    }
    if (tid < KCAP) {
        d_idx[e * KCAP + tid] = (int)sid[tid];
        d_G[e * KCAP + tid]   = __uint_as_float(sv[tid]);
    }
}

// ---------------- gather routed tokens -> fp16 ----------------
__global__ void gather_kernel(const float* __restrict__ x) {
    int r = blockIdx.x;
    int tok = d_idx[r];
    const float4* src = (const float4*)(x + (size_t)tok * HDIM);
    __half2* dst = (__half2*)(d_Xg + (size_t)r * HDIM);
    for (int i = threadIdx.x; i < HDIM / 4; i += blockDim.x) {
        float4 v = src[i];
        dst[i * 2]     = __floats2half2_rn(v.x, v.y);
        dst[i * 2 + 1] = __floats2half2_rn(v.z, v.w);
    }
}

// ---------------- fp16 mma.sync GEMM (m16n8k16, fp32 accum) ----------------
// C[M,N] = A[M,K]*B[K,N]. CTA 128x128, BK=64, 3-stage cp.async, 256 thr = 8 warps,
// warp tile 64x32 (warps 2Mx4N). ldmatrix fragment loads, XOR-swizzled smem.
// SEL 0: Xg*Wg -> d_G1f (fp32 raw)
// SEL 1: Xg*Wu -> d_Hh = fp16(silu(d_G1f+bg)*(acc+bu)), pad cols zeroed
// SEL 2: Hh*Wd -> atomicAdd(out[tok], g*(acc+bd))
#define ABYTES 16384            // 128 x 64 half
#define STG    32768            // + B 64 x 128 half
#define NS     3
#define DYN    (NS * STG)       // 98304

__device__ __forceinline__ void load_stage(uint32_t st, const __half* Ag, int lda,
                                           const __half* Bg, int ldb, int i, int tid) {
    const __half* Asrc = Ag + i * 64;
    const __half* Bsrc = Bg + (size_t)(i * 64) * ldb;
#pragma unroll
    for (int t = 0; t < 4; t++) {        // A: 128 rows x 8 chunks(16B)
        int idx = tid + t * 256;
        int m = idx >> 3, kc = idx & 7;
        uint32_t dst = st + (uint32_t)(m * 128) + (uint32_t)(((kc << 4)) ^ ((m & 7) << 4));
        cpasync16(dst, Asrc + (size_t)m * lda + kc * 8);
    }
#pragma unroll
    for (int t = 0; t < 4; t++) {        // B: 64 rows x 16 chunks(16B), swizzle per 128B half-row
        int idx = tid + t * 256;
        int k = idx >> 4, nc = idx & 15;
        uint32_t dst = st + (uint32_t)ABYTES + (uint32_t)(k * 256) + (uint32_t)((nc & 8) << 4)
                     + (uint32_t)((((nc & 7) << 4)) ^ ((k & 7) << 4));
        cpasync16(dst, Bsrc + (size_t)k * ldb + nc * 8);
    }
}

template <int SEL>
__global__ void __launch_bounds__(256) gemm_fp16(
    int K, int lda, int ldb,
    const float* __restrict__ bg, const float* __restrict__ bu,
    const float* __restrict__ bdn, float* __restrict__ out)
{
    extern __shared__ __align__(1024) char dsm[];
    const __half* A = (SEL == 2) ? d_Hh : d_Xg;
    const __half* B = (SEL == 0) ? d_Wg : (SEL == 1) ? d_Wu : d_Wd;

    uint32_t sbase = smem_u32(dsm);
    int tid = threadIdx.x, wid = tid >> 5, lane = tid & 31;
    int gp = lane >> 2, tg = lane & 3;
    int wm = (wid >> 2) * 64;            // 2 warp rows
    int wn = (wid & 3) * 32;             // 4 warp cols
    int bm = blockIdx.y * 128, bn = blockIdx.x * 128;

    const __half* Ag = A + (size_t)bm * lda;
    const __half* Bg = B + bn;
    const int NC = K >> 6;

    float c[4][4][4];
#pragma unroll
    for (int mi = 0; mi < 4; mi++)
#pragma unroll
        for (int ni = 0; ni < 4; ni++)
#pragma unroll
            for (int q = 0; q < 4; q++) c[mi][ni][q] = 0.0f;

    load_stage(sbase,       Ag, lda, Bg, ldb, 0, tid); CP_COMMIT();
    load_stage(sbase + STG, Ag, lda, Bg, ldb, 1, tid); CP_COMMIT();

    int mat = lane >> 3, r8 = lane & 7;

    for (int i = 0; i < NC; i++) {
        CP_WAIT1();
        __syncthreads();
        if (i + 2 < NC) load_stage(sbase + ((i + 2) % NS) * STG, Ag, lda, Bg, ldb, i + 2, tid);
        CP_COMMIT();

        uint32_t abase = sbase + (i % NS) * STG;
        uint32_t bbase = abase + ABYTES;

#pragma unroll
        for (int ks = 0; ks < 4; ks++) {
            int kk = ks * 16;
            uint32_t a[4][4], b[4][2];
#pragma unroll
            for (int mi = 0; mi < 4; mi++) {
                int m = wm + mi * 16 + r8 + (mat & 1) * 8;
                int kc = (kk >> 3) + (mat >> 1);
                uint32_t addr = abase + (uint32_t)(m * 128) + (uint32_t)(((kc << 4)) ^ ((m & 7) << 4));
                ldm_x4(a[mi], addr);
            }
#pragma unroll
            for (int nj = 0; nj < 2; nj++) {
                int kq = kk + (mat & 1) * 8 + r8;
                int n  = wn + nj * 16 + (mat >> 1) * 8;
                uint32_t addr = bbase + (uint32_t)(kq * 256) + (uint32_t)((n & 64) << 1)
                              + (uint32_t)(((((n >> 3) & 7) << 4)) ^ ((kq & 7) << 4));
                uint32_t t4[4];
                ldm_x4_t(t4, addr);
                b[nj * 2 + 0][0] = t4[0]; b[nj * 2 + 0][1] = t4[1];
                b[nj * 2 + 1][0] = t4[2]; b[nj * 2 + 1][1] = t4[3];
            }
#pragma unroll
            for (int mi = 0; mi < 4; mi++)
#pragma unroll
                for (int ni = 0; ni < 4; ni++)
                    mma16816(c[mi][ni], a[mi], b[ni]);
        }
    }

    // ---------------- epilogue ----------------
#pragma unroll
    for (int mi = 0; mi < 4; mi++) {
        int row = bm + wm + mi * 16 + gp;
        int tok0 = 0, tok1 = 0; float g0 = 0.f, g1 = 0.f;
        if (SEL == 2) {
            tok0 = d_idx[row];     g0 = d_G[row];
            tok1 = d_idx[row + 8]; g1 = d_G[row + 8];
        }
#pragma unroll
        for (int ni = 0; ni < 4; ni++) {
            int col = bn + wn + ni * 8 + 2 * tg;
            if (SEL == 0) {
                *(float2*)(d_G1f + (size_t)row * NPAD + col)       = make_float2(c[mi][ni][0], c[mi][ni][1]);
                *(float2*)(d_G1f + (size_t)(row + 8) * NPAD + col) = make_float2(c[mi][ni][2], c[mi][ni][3]);
            } else if (SEL == 1) {
#pragma unroll
                for (int h = 0; h < 2; h++) {
                    int r2 = row + h * 8;
                    float2 gv = *(const float2*)(d_G1f + (size_t)r2 * NPAD + col);
                    float o0 = 0.f, o1 = 0.f;
                    if (col < DFF) {
                        float gate = gv.x + bg[col];
                        float up   = c[mi][ni][h * 2 + 0] + bu[col];
                        o0 = gate * (1.0f / (1.0f + expf(-gate))) * up;
                    }
                    if (col + 1 < DFF) {
                        float gate = gv.y + bg[col + 1];
                        float up   = c[mi][ni][h * 2 + 1] + bu[col + 1];
                        o1 = gate * (1.0f / (1.0f + expf(-gate))) * up;
                    }
                    *(__half2*)(d_Hh + (size_t)r2 * NPAD + col) = __floats2half2_rn(o0, o1);
                }
            } else {
                float b0 = bdn[col], b1 = bdn[col + 1];
                float* o0 = out + (size_t)tok0 * HDIM + col;
                atomicAdd(o0,     g0 * (c[mi][ni][0] + b0));
                atomicAdd(o0 + 1, g0 * (c[mi][ni][1] + b1));
                float* o1 = out + (size_t)tok1 * HDIM + col;
                atomicAdd(o1,     g1 * (c[mi][ni][2] + b0));
                atomicAdd(o1 + 1, g1 * (c[mi][ni][3] + b1));
            }
        }
    }
}

// ---------------- launch ----------------
extern "C" void kernel_launch(void* const* d_in, const int* in_sizes, int n_in,
                              void* d_out, int out_size) {
    const float* x  = (const float*)d_in[0];
    const float* rw = (const float*)d_in[1];
    const float* rb = (const float*)d_in[2];
    const float* wg = (const float*)d_in[3];
    const float* bg = (const float*)d_in[4];
    const float* wu = (const float*)d_in[5];
    const float* bu = (const float*)d_in[6];
    const float* wd = (const float*)d_in[7];
    const float* bd = (const float*)d_in[8];
    float* out = (float*)d_out;

    cudaFuncSetAttribute(gemm_fp16<0>, cudaFuncAttributeMaxDynamicSharedMemorySize, DYN);
    cudaFuncSetAttribute(gemm_fp16<1>, cudaFuncAttributeMaxDynamicSharedMemorySize, DYN);
    cudaFuncSetAttribute(gemm_fp16<2>, cudaFuncAttributeMaxDynamicSharedMemorySize, DYN);

    zero_kernel<<<((size_t)out_size + 255) / 256, 256>>>(out, (size_t)out_size);

    int totGU = HDIM * NPAD;
    int totD  = NPAD * HDIM;
    padconv_kernel<0><<<(totGU + 255) / 256, 256>>>(wg, totGU);
    padconv_kernel<1><<<(totGU + 255) / 256, 256>>>(wu, totGU);
    padconv_kernel<2><<<(totD  + 255) / 256, 256>>>(wd, totD);

    gumbel_kernel<<<(NTOK * NEXP + 255) / 256, 256>>>();
    router_kernel<<<NTOK / 8, 256>>>(x, rw, rb);
    topk_kernel<<<NEXP, 1024>>>();
    gather_kernel<<<NSLOT, 256>>>(x);

    dim3 g12(NPAD / 128, NSLOT / 128);   // (43, 64)
    gemm_fp16<0><<<g12, 256, DYN>>>(HDIM, HDIM, NPAD, nullptr, nullptr, nullptr, nullptr);
    gemm_fp16<1><<<g12, 256, DYN>>>(HDIM, HDIM, NPAD, bg, bu, nullptr, nullptr);

    dim3 g3(HDIM / 128, NSLOT / 128);    // (16, 64)
    gemm_fp16<2><<<g3, 256, DYN>>>(NPAD, NPAD, HDIM, nullptr, nullptr, bd, out);
}

// round 5
// speedup vs baseline: 3.0212x; 1.0214x over previous
#include <cuda_runtime.h>
#include <cuda_fp16.h>
#include <cstdint>
#include <cstddef>

#define NTOK 8192
#define HDIM 2048
#define NEXP 8
#define KCAP 1024
#define DFF  5461
#define NPAD 5504
#define NSLOT 8192   // NEXP * KCAP

// ---------------- device scratch (static, no allocations) ----------------
__device__ float  d_gum[NTOK * NEXP];
__device__ float  d_Sm [NEXP * NTOK];            // transposed: [expert][token]
__device__ int    d_cnt[NEXP];
__device__ int    d_idx[NSLOT];
__device__ float  d_G  [NSLOT];
__device__ __half d_Xg [(size_t)NSLOT * HDIM];   // gathered tokens fp16
__device__ __half d_Wg [(size_t)HDIM * NPAD];    // w_gate  [K=2048][N=5504] fp16
__device__ __half d_Wu [(size_t)HDIM * NPAD];    // w_up
__device__ __half d_Wd [(size_t)NPAD * HDIM];    // w_down  [K=5504][N=2048] fp16
__device__ __half d_Hh [(size_t)NSLOT * NPAD];   // silu(g)*up fp16

// ---------------- helpers ----------------
__device__ __forceinline__ uint32_t smem_u32(const void* p) {
    uint32_t a;
    asm("{ .reg .u64 t; cvta.to.shared.u64 t, %1; cvt.u32.u64 %0, t; }" : "=r"(a) : "l"(p));
    return a;
}
__device__ __forceinline__ void cpasync16(uint32_t dst, const void* src) {
    asm volatile("cp.async.cg.shared.global [%0], [%1], 16;" :: "r"(dst), "l"(src) : "memory");
}
#define CP_COMMIT()  asm volatile("cp.async.commit_group;" ::: "memory")
#define CP_WAIT1()   asm volatile("cp.async.wait_group 1;" ::: "memory")

__device__ __forceinline__ void ldm_x4(uint32_t* r, uint32_t a) {
    asm volatile("ldmatrix.sync.aligned.m8n8.x4.shared.b16 {%0,%1,%2,%3}, [%4];"
                 : "=r"(r[0]), "=r"(r[1]), "=r"(r[2]), "=r"(r[3]) : "r"(a));
}
__device__ __forceinline__ void ldm_x4_t(uint32_t* r, uint32_t a) {
    asm volatile("ldmatrix.sync.aligned.m8n8.x4.trans.shared.b16 {%0,%1,%2,%3}, [%4];"
                 : "=r"(r[0]), "=r"(r[1]), "=r"(r[2]), "=r"(r[3]) : "r"(a));
}
__device__ __forceinline__ void mma16816(float* c, const uint32_t* a, const uint32_t* b) {
    asm volatile(
        "mma.sync.aligned.m16n8k16.row.col.f32.f16.f16.f32 "
        "{%0,%1,%2,%3}, {%4,%5,%6,%7}, {%8,%9}, {%0,%1,%2,%3};"
        : "+f"(c[0]), "+f"(c[1]), "+f"(c[2]), "+f"(c[3])
        : "r"(a[0]), "r"(a[1]), "r"(a[2]), "r"(a[3]), "r"(b[0]), "r"(b[1]));
}

// ---------------- zero output (float4) ----------------
__global__ void zero_kernel(float4* p, size_t n4) {
    size_t i = (size_t)blockIdx.x * blockDim.x + threadIdx.x;
    if (i < n4) p[i] = make_float4(0.f, 0.f, 0.f, 0.f);
}

// ---------------- pad + fp16-convert weights ----------------
template <int SEL>
__global__ void padconv_kernel(const float* __restrict__ src, int total) {
    int i = blockIdx.x * blockDim.x + threadIdx.x;
    if (i >= total) return;
    float v = 0.0f;
    if (SEL < 2) {
        int r = i / NPAD, c = i - r * NPAD;
        if (c < DFF) v = src[(size_t)r * DFF + c];
    } else {
        int r = i / HDIM;
        if (r < DFF) v = src[i];
    }
    __half* dst = (SEL == 0) ? d_Wg : (SEL == 1) ? d_Wu : d_Wd;
    dst[i] = __float2half_rn(v);
}

// ---------------- Gumbel noise: JAX threefry2x32 (+ zero d_cnt) ----------------
__global__ void gumbel_kernel() {
    unsigned i = blockIdx.x * blockDim.x + threadIdx.x;
    if (i < NEXP) d_cnt[i] = 0;
    if (i >= NTOK * NEXP) return;
    const uint32_t ks0 = 0u, ks1 = 42u, ks2 = 0u ^ 42u ^ 0x1BD11BDAu;
    uint32_t x0 = 0u + ks0;
    uint32_t x1 = i  + ks1;
#define TF_RND(r) { x0 += x1; x1 = (x1 << (r)) | (x1 >> (32 - (r))); x1 ^= x0; }
    TF_RND(13) TF_RND(15) TF_RND(26) TF_RND(6)   x0 += ks1; x1 += ks2 + 1u;
    TF_RND(17) TF_RND(29) TF_RND(16) TF_RND(24)  x0 += ks2; x1 += ks0 + 2u;
    TF_RND(13) TF_RND(15) TF_RND(26) TF_RND(6)   x0 += ks0; x1 += ks1 + 3u;
    TF_RND(17) TF_RND(29) TF_RND(16) TF_RND(24)  x0 += ks1; x1 += ks2 + 4u;
    TF_RND(13) TF_RND(15) TF_RND(26) TF_RND(6)   x0 += ks2; x1 += ks0 + 5u;
#undef TF_RND
    uint32_t bits = x0 ^ x1;
    float u = __uint_as_float((bits >> 9) | 0x3F800000u) - 1.0f;
    d_gum[i] = -logf(-logf(u + 1e-10f) + 1e-10f);
}

// ---------------- router (writes Sm transposed) ----------------
__global__ void router_kernel(const float* __restrict__ x,
                              const float* __restrict__ rw,
                              const float* __restrict__ rb) {
    int gw = (blockIdx.x * blockDim.x + threadIdx.x) >> 5;
    int lane = threadIdx.x & 31;
    if (gw >= NTOK) return;
    const float* xr = x + (size_t)gw * HDIM;
    double acc[NEXP];
#pragma unroll
    for (int e = 0; e < NEXP; e++) acc[e] = 0.0;
    for (int h = lane; h < HDIM; h += 32) {
        float xv = xr[h];
        const float4* w4 = (const float4*)(rw + (size_t)h * NEXP);
        float4 w0 = w4[0], w1 = w4[1];
        acc[0] += (double)xv * w0.x; acc[1] += (double)xv * w0.y;
        acc[2] += (double)xv * w0.z; acc[3] += (double)xv * w0.w;
        acc[4] += (double)xv * w1.x; acc[5] += (double)xv * w1.y;
        acc[6] += (double)xv * w1.z; acc[7] += (double)xv * w1.w;
    }
#pragma unroll
    for (int off = 16; off; off >>= 1)
#pragma unroll
        for (int e = 0; e < NEXP; e++)
            acc[e] += __shfl_xor_sync(0xffffffffu, acc[e], off);
    if (lane == 0) {
        float hh[NEXP]; float mx = -1e30f;
#pragma unroll
        for (int e = 0; e < NEXP; e++) {
            hh[e] = (float)acc[e] + rb[e] + d_gum[gw * NEXP + e];
            mx = fmaxf(mx, hh[e]);
        }
        float s = 0.0f;
#pragma unroll
        for (int e = 0; e < NEXP; e++) { hh[e] = expf(hh[e] - mx); s += hh[e]; }
        float inv = 1.0f / s;
#pragma unroll
        for (int e = 0; e < NEXP; e++) d_Sm[(size_t)e * NTOK + gw] = hh[e] * inv;
    }
}

// ---------------- rank-select top-k (set semantics; order-free) ----------------
// grid: 64 CTAs = 8 experts x 8 chunks of 1024 tokens. rank(i) < KCAP -> selected.
__global__ void __launch_bounds__(1024) rank_topk_kernel() {
    __shared__ float sval[NTOK];   // 32 KB
    int e = blockIdx.x >> 3;
    int chunk = blockIdx.x & 7;
    int tid = threadIdx.x;
    const float* Se = d_Sm + (size_t)e * NTOK;
    for (int i = tid; i < NTOK; i += 1024) sval[i] = Se[i];
    __syncthreads();
    int t = chunk * 1024 + tid;
    float v = sval[t];
    int rank = 0;
#pragma unroll 8
    for (int j = 0; j < NTOK; j++) {
        float vj = sval[j];
        rank += (vj > v) || (vj == v && j < t);
    }
    if (rank < KCAP) {
        int pos = atomicAdd(&d_cnt[e], 1);
        d_idx[e * KCAP + pos] = t;
        d_G[e * KCAP + pos]   = v;
    }
}

// ---------------- gather routed tokens -> fp16 ----------------
__global__ void gather_kernel(const float* __restrict__ x) {
    int r = blockIdx.x;
    int tok = d_idx[r];
    const float4* src = (const float4*)(x + (size_t)tok * HDIM);
    __half2* dst = (__half2*)(d_Xg + (size_t)r * HDIM);
    for (int i = threadIdx.x; i < HDIM / 4; i += blockDim.x) {
        float4 v = src[i];
        dst[i * 2]     = __floats2half2_rn(v.x, v.y);
        dst[i * 2 + 1] = __floats2half2_rn(v.z, v.w);
    }
}

// =============== fused GEMM1+2: Xg*[Wg|Wu] -> silu(g+bg)*(u+bu) -> d_Hh ===============
// CTA tile 128(M) x 64(N) with TWO B matrices. BK=64, 3-stage cp.async, 256 thr.
// 8 warps = 4Mx2N grid, warp tile 32x32 per output tensor.
#define F_AB   16384                 // A 128x64 half
#define F_BB   8192                  // each B 64x64 half
#define F_STG  (F_AB + 2 * F_BB)     // 32768
#define NS     3
#define DYN    (NS * F_STG)          // 98304

__device__ __forceinline__ void load_stage12(uint32_t st, const __half* Ag,
                                             const __half* Bg, const __half* Bu,
                                             int i, int tid) {
    const __half* Asrc = Ag + i * 64;
    const __half* Bgs = Bg + (size_t)(i * 64) * NPAD;
    const __half* Bus = Bu + (size_t)(i * 64) * NPAD;
#pragma unroll
    for (int t = 0; t < 4; t++) {        // A: 128 rows x 8 chunks
        int idx = tid + t * 256;
        int m = idx >> 3, kc = idx & 7;
        uint32_t dst = st + (uint32_t)(m * 128) + (uint32_t)((kc << 4) ^ ((m & 7) << 4));
        cpasync16(dst, Asrc + (size_t)m * HDIM + kc * 8);
    }
#pragma unroll
    for (int t = 0; t < 2; t++) {        // Bg: 64 rows x 8 chunks
        int idx = tid + t * 256;
        int k = idx >> 3, nc = idx & 7;
        uint32_t dst = st + F_AB + (uint32_t)(k * 128) + (uint32_t)((nc << 4) ^ ((k & 7) << 4));
        cpasync16(dst, Bgs + (size_t)k * NPAD + nc * 8);
    }
#pragma unroll
    for (int t = 0; t < 2; t++) {        // Bu: 64 rows x 8 chunks
        int idx = tid + t * 256;
        int k = idx >> 3, nc = idx & 7;
        uint32_t dst = st + F_AB + F_BB + (uint32_t)(k * 128) + (uint32_t)((nc << 4) ^ ((k & 7) << 4));
        cpasync16(dst, Bus + (size_t)k * NPAD + nc * 8);
    }
}

__global__ void __launch_bounds__(256) gemm_fused12(
    const float* __restrict__ bg, const float* __restrict__ bu)
{
    extern __shared__ __align__(1024) char dsm[];
    uint32_t sbase = smem_u32(dsm);
    int tid = threadIdx.x, wid = tid >> 5, lane = tid & 31;
    int gp = lane >> 2, tg = lane & 3;
    int wm = (wid >> 1) * 32;            // 4 warp rows
    int wn = (wid & 1) * 32;             // 2 warp cols
    int bm = blockIdx.y * 128, bn = blockIdx.x * 64;

    const __half* Ag = d_Xg + (size_t)bm * HDIM;
    const __half* Bg = d_Wg + bn;
    const __half* Bu = d_Wu + bn;
    const int NC = HDIM >> 6;            // 32

    float cg[2][4][4], cu[2][4][4];
#pragma unroll
    for (int mi = 0; mi < 2; mi++)
#pragma unroll
        for (int ni = 0; ni < 4; ni++)
#pragma unroll
            for (int q = 0; q < 4; q++) { cg[mi][ni][q] = 0.f; cu[mi][ni][q] = 0.f; }

    load_stage12(sbase,         Ag, Bg, Bu, 0, tid); CP_COMMIT();
    load_stage12(sbase + F_STG, Ag, Bg, Bu, 1, tid); CP_COMMIT();

    int mat = lane >> 3, r8 = lane & 7;

    for (int i = 0; i < NC; i++) {
        CP_WAIT1();
        __syncthreads();
        if (i + 2 < NC) load_stage12(sbase + ((i + 2) % NS) * F_STG, Ag, Bg, Bu, i + 2, tid);
        CP_COMMIT();

        uint32_t abase = sbase + (i % NS) * F_STG;
        uint32_t gbase = abase + F_AB;
        uint32_t ubase = gbase + F_BB;

#pragma unroll
        for (int ks = 0; ks < 4; ks++) {
            int kk = ks * 16;
            uint32_t a[2][4], bG[4][2], bU[4][2];
#pragma unroll
            for (int mi = 0; mi < 2; mi++) {
                int m = wm + mi * 16 + r8 + (mat & 1) * 8;
                int kc = (kk >> 3) + (mat >> 1);
                uint32_t addr = abase + (uint32_t)(m * 128) + (uint32_t)((kc << 4) ^ ((m & 7) << 4));
                ldm_x4(a[mi], addr);
            }
            int kq = kk + (mat & 1) * 8 + r8;
#pragma unroll
            for (int nj = 0; nj < 2; nj++) {
                int n = wn + nj * 16 + (mat >> 1) * 8;
                uint32_t off = (uint32_t)(kq * 128) + (uint32_t)((((n >> 3) & 7) << 4) ^ ((kq & 7) << 4));
                uint32_t t4[4];
                ldm_x4_t(t4, gbase + off);
                bG[nj * 2 + 0][0] = t4[0]; bG[nj * 2 + 0][1] = t4[1];
                bG[nj * 2 + 1][0] = t4[2]; bG[nj * 2 + 1][1] = t4[3];
                ldm_x4_t(t4, ubase + off);
                bU[nj * 2 + 0][0] = t4[0]; bU[nj * 2 + 0][1] = t4[1];
                bU[nj * 2 + 1][0] = t4[2]; bU[nj * 2 + 1][1] = t4[3];
            }
#pragma unroll
            for (int mi = 0; mi < 2; mi++)
#pragma unroll
                for (int ni = 0; ni < 4; ni++) {
                    mma16816(cg[mi][ni], a[mi], bG[ni]);
                    mma16816(cu[mi][ni], a[mi], bU[ni]);
                }
        }
    }

    // epilogue: silu(gate+bg)*(up+bu) -> d_Hh (pad cols zeroed)
#pragma unroll
    for (int mi = 0; mi < 2; mi++) {
        int row = bm + wm + mi * 16 + gp;
#pragma unroll
        for (int ni = 0; ni < 4; ni++) {
            int col = bn + wn + ni * 8 + 2 * tg;
            float b0g = 0.f, b1g = 0.f, b0u = 0.f, b1u = 0.f;
            bool v0 = col < DFF, v1 = (col + 1) < DFF;
            if (v0) { b0g = bg[col];     b0u = bu[col]; }
            if (v1) { b1g = bg[col + 1]; b1u = bu[col + 1]; }
#pragma unroll
            for (int h = 0; h < 2; h++) {
                int r2 = row + h * 8;
                float o0 = 0.f, o1 = 0.f;
                if (v0) {
                    float gate = cg[mi][ni][h * 2 + 0] + b0g;
                    float up   = cu[mi][ni][h * 2 + 0] + b0u;
                    o0 = gate * (1.0f / (1.0f + expf(-gate))) * up;
                }
                if (v1) {
                    float gate = cg[mi][ni][h * 2 + 1] + b1g;
                    float up   = cu[mi][ni][h * 2 + 1] + b1u;
                    o1 = gate * (1.0f / (1.0f + expf(-gate))) * up;
                }
                *(__half2*)(d_Hh + (size_t)r2 * NPAD + col) = __floats2half2_rn(o0, o1);
            }
        }
    }
}

// =============== GEMM3: Hh * Wd -> atomicAdd(out) (round-4 layout) ===============
#define ABYTES 16384            // 128 x 64 half
#define STG3   32768            // + B 64 x 128 half

__device__ __forceinline__ void load_stage3(uint32_t st, const __half* Ag,
                                            const __half* Bg, int i, int tid) {
    const __half* Asrc = Ag + i * 64;
    const __half* Bsrc = Bg + (size_t)(i * 64) * HDIM;
#pragma unroll
    for (int t = 0; t < 4; t++) {
        int idx = tid + t * 256;
        int m = idx >> 3, kc = idx & 7;
        uint32_t dst = st + (uint32_t)(m * 128) + (uint32_t)((kc << 4) ^ ((m & 7) << 4));
        cpasync16(dst, Asrc + (size_t)m * NPAD + kc * 8);
    }
#pragma unroll
    for (int t = 0; t < 4; t++) {
        int idx = tid + t * 256;
        int k = idx >> 4, nc = idx & 15;
        uint32_t dst = st + (uint32_t)ABYTES + (uint32_t)(k * 256) + (uint32_t)((nc & 8) << 4)
                     + (uint32_t)(((nc & 7) << 4) ^ ((k & 7) << 4));
        cpasync16(dst, Bsrc + (size_t)k * HDIM + nc * 8);
    }
}

__global__ void __launch_bounds__(256) gemm3(
    const float* __restrict__ bdn, float* __restrict__ out)
{
    extern __shared__ __align__(1024) char dsm[];
    uint32_t sbase = smem_u32(dsm);
    int tid = threadIdx.x, wid = tid >> 5, lane = tid & 31;
    int gp = lane >> 2, tg = lane & 3;
    int wm = (wid >> 2) * 64;
    int wn = (wid & 3) * 32;
    int bm = blockIdx.y * 128, bn = blockIdx.x * 128;

    const __half* Ag = d_Hh + (size_t)bm * NPAD;
    const __half* Bg = d_Wd + bn;
    const int NC = NPAD >> 6;    // 86

    float c[4][4][4];
#pragma unroll
    for (int mi = 0; mi < 4; mi++)
#pragma unroll
        for (int ni = 0; ni < 4; ni++)
#pragma unroll
            for (int q = 0; q < 4; q++) c[mi][ni][q] = 0.0f;

    load_stage3(sbase,        Ag, Bg, 0, tid); CP_COMMIT();
    load_stage3(sbase + STG3, Ag, Bg, 1, tid); CP_COMMIT();

    int mat = lane >> 3, r8 = lane & 7;

    for (int i = 0; i < NC; i++) {
        CP_WAIT1();
        __syncthreads();
        if (i + 2 < NC) load_stage3(sbase + ((i + 2) % NS) * STG3, Ag, Bg, i + 2, tid);
        CP_COMMIT();

        uint32_t abase = sbase + (i % NS) * STG3;
        uint32_t bbase = abase + ABYTES;

#pragma unroll
        for (int ks = 0; ks < 4; ks++) {
            int kk = ks * 16;
            uint32_t a[4][4], b[4][2];
#pragma unroll
            for (int mi = 0; mi < 4; mi++) {
                int m = wm + mi * 16 + r8 + (mat & 1) * 8;
                int kc = (kk >> 3) + (mat >> 1);
                uint32_t addr = abase + (uint32_t)(m * 128) + (uint32_t)((kc << 4) ^ ((m & 7) << 4));
                ldm_x4(a[mi], addr);
            }
#pragma unroll
            for (int nj = 0; nj < 2; nj++) {
                int kq = kk + (mat & 1) * 8 + r8;
                int n  = wn + nj * 16 + (mat >> 1) * 8;
                uint32_t addr = bbase + (uint32_t)(kq * 256) + (uint32_t)((n & 64) << 1)
                              + (uint32_t)(((((n >> 3) & 7) << 4)) ^ ((kq & 7) << 4));
                uint32_t t4[4];
                ldm_x4_t(t4, addr);
                b[nj * 2 + 0][0] = t4[0]; b[nj * 2 + 0][1] = t4[1];
                b[nj * 2 + 1][0] = t4[2]; b[nj * 2 + 1][1] = t4[3];
            }
#pragma unroll
            for (int mi = 0; mi < 4; mi++)
#pragma unroll
                for (int ni = 0; ni < 4; ni++)
                    mma16816(c[mi][ni], a[mi], b[ni]);
        }
    }

#pragma unroll
    for (int mi = 0; mi < 4; mi++) {
        int row = bm + wm + mi * 16 + gp;
        int tok0 = d_idx[row];     float g0 = d_G[row];
        int tok1 = d_idx[row + 8]; float g1 = d_G[row + 8];
#pragma unroll
        for (int ni = 0; ni < 4; ni++) {
            int col = bn + wn + ni * 8 + 2 * tg;
            float b0 = bdn[col], b1 = bdn[col + 1];
            float* o0 = out + (size_t)tok0 * HDIM + col;
            atomicAdd(o0,     g0 * (c[mi][ni][0] + b0));
            atomicAdd(o0 + 1, g0 * (c[mi][ni][1] + b1));
            float* o1 = out + (size_t)tok1 * HDIM + col;
            atomicAdd(o1,     g1 * (c[mi][ni][2] + b0));
            atomicAdd(o1 + 1, g1 * (c[mi][ni][3] + b1));
        }
    }
}

// ---------------- launch ----------------
extern "C" void kernel_launch(void* const* d_in, const int* in_sizes, int n_in,
                              void* d_out, int out_size) {
    const float* x  = (const float*)d_in[0];
    const float* rw = (const float*)d_in[1];
    const float* rb = (const float*)d_in[2];
    const float* wg = (const float*)d_in[3];
    const float* bg = (const float*)d_in[4];
    const float* wu = (const float*)d_in[5];
    const float* bu = (const float*)d_in[6];
    const float* wd = (const float*)d_in[7];
    const float* bd = (const float*)d_in[8];
    float* out = (float*)d_out;

    cudaFuncSetAttribute(gemm_fused12, cudaFuncAttributeMaxDynamicSharedMemorySize, DYN);
    cudaFuncSetAttribute(gemm3,        cudaFuncAttributeMaxDynamicSharedMemorySize, DYN);

    size_t n4 = (size_t)out_size / 4;
    zero_kernel<<<(n4 + 255) / 256, 256>>>((float4*)out, n4);

    int totGU = HDIM * NPAD;
    int totD  = NPAD * HDIM;
    padconv_kernel<0><<<(totGU + 255) / 256, 256>>>(wg, totGU);
    padconv_kernel<1><<<(totGU + 255) / 256, 256>>>(wu, totGU);
    padconv_kernel<2><<<(totD  + 255) / 256, 256>>>(wd, totD);

    gumbel_kernel<<<(NTOK * NEXP + 255) / 256, 256>>>();
    router_kernel<<<NTOK / 8, 256>>>(x, rw, rb);
    rank_topk_kernel<<<64, 1024>>>();
    gather_kernel<<<NSLOT, 256>>>(x);

    dim3 g12(NPAD / 64, NSLOT / 128);    // (86, 64)
    gemm_fused12<<<g12, 256, DYN>>>(bg, bu);

    dim3 g3(HDIM / 128, NSLOT / 128);    // (16, 64)
    gemm3<<<g3, 256, DYN>>>(bd, out);
}